// round 11
// baseline (speedup 1.0000x reference)
#include <cuda_runtime.h>

// MxAssemble: out[b,c,y,x] = sum_{dy,dx in [0,13)} aff[b, dy*13+dx, y, x] * in2zp[b, c, y+dy-6, x+dx-6]
// B=4, D=169, C=64, H=W=192, fp32.
// f32x2-packed inner product. Occupancy-first shape: CBLK=8, TH=16 ->
// smem 70KB, 3 blocks/SM (24 warps). dx loop split into 3 j-chunks so the
// aff register cache stays <= 20 regs (85-reg budget for 3x256 threads).

#define BB   4
#define CC   64
#define HH   192
#define WW   192
#define WIN  13
#define DD   169
#define HWSZ (HH*WW)

#define TW    64     // x pixels per block
#define TH    16     // y rows per block
#define CBLK  8      // channels per block
#define CPT   8      // channels per thread
#define XR    4      // x pixels per thread
#define SROWS (TH+12)   // 28
#define SPITCH 80       // floats per smem row (320B, 16B aligned)

typedef unsigned long long u64t;

__device__ __forceinline__ u64t ffma2(u64t a, u64t b, u64t c) {
    u64t d;
    asm("fma.rn.f32x2 %0, %1, %2, %3;" : "=l"(d) : "l"(a), "l"(b), "l"(c));
    return d;
}
__device__ __forceinline__ u64t packf2(float lo, float hi) {
    u64t d;
    asm("mov.b64 %0, {%1, %2};" : "=l"(d) : "f"(lo), "f"(hi));
    return d;
}
__device__ __forceinline__ void unpackf2(u64t v, float& lo, float& hi) {
    asm("mov.b64 {%0, %1}, %2;" : "=f"(lo), "=f"(hi) : "l"(v));
}

union QU { ulonglong2 u; float4 f; };

__global__ __launch_bounds__(256, 3)
void mxassemble_kernel(const float* __restrict__ aff,
                       const float* __restrict__ in2,
                       float* __restrict__ out)
{
    __shared__ __align__(16) float s[CBLK][SROWS][SPITCH];   // 70 KB

    const int tx = threadIdx.x;      // 0..15  -> x group
    const int yy = threadIdx.y;      // 0..15  -> row within tile

    const int bx = blockIdx.x;       // 24 = 8 cgroups * 3 xtiles, cgroup fastest
    const int cg = bx & 7;
    const int xt = bx >> 3;
    const int yt = blockIdx.y;       // 0..11
    const int b  = blockIdx.z;       // 0..3

    const int x0 = xt * TW;
    const int y0 = yt * TH;
    const int c0 = cg * CBLK;

    // ---- cooperative smem fill -------------------------------------------
    // 4480 quads = 8 planes x 28 rows x 20 aligned global quads (gxq = x0-8+4q).
    // idx = cc*560 + rr*20 + q ; advance 256 = 12*20 + 16 with carry fixups.
    {
        const float* in2b = in2 + (size_t)b * CC * HWSZ;
        const int tid = yy * 16 + tx;          // 0..255
        int q  = tid % 20;
        int rr = tid / 20;                     // < 13, so rr ok, cc = 0
        int cc = 0;
        #pragma unroll 1
        for (int it = 0; it < 18; it++) {
            if (it < 17 || tid < 128) {        // 17*256 + 128 = 4480
                const int gy  = y0 - 6 + rr;
                const int gxq = x0 - 8 + 4 * q;

                float4 v = make_float4(0.f, 0.f, 0.f, 0.f);
                if ((unsigned)gy < (unsigned)HH) {
                    const float* src = in2b + (size_t)(c0 + cc) * HWSZ + gy * WW + gxq;
                    if (gxq >= 0 && gxq <= WW - 4) {
                        v = *(const float4*)src;
                    } else {
                        if ((unsigned)(gxq + 0) < (unsigned)WW) v.x = src[0];
                        if ((unsigned)(gxq + 1) < (unsigned)WW) v.y = src[1];
                        if ((unsigned)(gxq + 2) < (unsigned)WW) v.z = src[2];
                        if ((unsigned)(gxq + 3) < (unsigned)WW) v.w = src[3];
                    }
                }
                const int c0q = 4 * q - 2;               // smem col of v.x
                float* dst = &s[cc][rr][0];
                if (c0q >= 0) *(float2*)(dst + c0q) = make_float2(v.x, v.y);
                *(float2*)(dst + c0q + 2) = make_float2(v.z, v.w);
            }
            q += 16; rr += 12;
            if (q >= 20)    { q -= 20; rr += 1; }
            if (rr >= SROWS){ rr -= SROWS; cc += 1; }
        }
    }
    __syncthreads();

    // ---- main accumulation ------------------------------------------------
    u64t accA[CPT], accB[CPT];       // accA: outputs (xs, xs+1), accB: (xs+2, xs+3)
    #pragma unroll
    for (int c = 0; c < CPT; c++) { accA[c] = 0ull; accB[c] = 0ull; }

    const int xs = tx * XR;
    const float* affRow = aff + (size_t)b * DD * HWSZ + (y0 + yy) * WW + x0 + xs;
    const float* sdy = &s[0][yy][xs];   // rolling smem base; +SPITCH per dy

    #pragma unroll 1
    for (int dy = 0; dy < WIN; dy++) {
        // ======== chunk A: j = 0..3  (needs cols xs..xs+6 -> Q0,Q1) ========
        {
            ulonglong2 ap[4];
            #pragma unroll
            for (int j = 0; j < 4; j++)
                ap[j] = *(const ulonglong2*)(affRow + j * HWSZ);
            #pragma unroll
            for (int c = 0; c < CPT; c++) {
                const float* sr = sdy + c * (SROWS * SPITCH);
                QU q0, q1;
                q0.u = *(const ulonglong2*)(sr);
                q1.u = *(const ulonglong2*)(sr + 4);
                const u64t p0 = q0.u.x, p2 = q0.u.y, p4 = q1.u.x;
                const u64t p1 = packf2(q0.f.y, q0.f.z);
                const u64t p3 = packf2(q0.f.w, q1.f.x);
                const u64t p5 = packf2(q1.f.y, q1.f.z);
                accA[c] = ffma2(ap[0].x, p0, accA[c]);  accB[c] = ffma2(ap[0].y, p2, accB[c]);
                accA[c] = ffma2(ap[1].x, p1, accA[c]);  accB[c] = ffma2(ap[1].y, p3, accB[c]);
                accA[c] = ffma2(ap[2].x, p2, accA[c]);  accB[c] = ffma2(ap[2].y, p4, accB[c]);
                accA[c] = ffma2(ap[3].x, p3, accA[c]);  accB[c] = ffma2(ap[3].y, p5, accB[c]);
            }
        }
        // ======== chunk B: j = 4..7  (cols xs+4..xs+10 -> Q1,Q2) ===========
        {
            ulonglong2 ap[4];
            #pragma unroll
            for (int j = 0; j < 4; j++)
                ap[j] = *(const ulonglong2*)(affRow + (4 + j) * HWSZ);
            #pragma unroll
            for (int c = 0; c < CPT; c++) {
                const float* sr = sdy + c * (SROWS * SPITCH);
                QU q1, q2;
                q1.u = *(const ulonglong2*)(sr + 4);
                q2.u = *(const ulonglong2*)(sr + 8);
                const u64t p4 = q1.u.x, p6 = q1.u.y, p8 = q2.u.x;
                const u64t p5 = packf2(q1.f.y, q1.f.z);
                const u64t p7 = packf2(q1.f.w, q2.f.x);
                const u64t p9 = packf2(q2.f.y, q2.f.z);
                accA[c] = ffma2(ap[0].x, p4, accA[c]);  accB[c] = ffma2(ap[0].y, p6, accB[c]);
                accA[c] = ffma2(ap[1].x, p5, accA[c]);  accB[c] = ffma2(ap[1].y, p7, accB[c]);
                accA[c] = ffma2(ap[2].x, p6, accA[c]);  accB[c] = ffma2(ap[2].y, p8, accB[c]);
                accA[c] = ffma2(ap[3].x, p7, accA[c]);  accB[c] = ffma2(ap[3].y, p9, accB[c]);
            }
        }
        // ======== chunk C: j = 8..12 (cols xs+8..xs+15 -> Q2,Q3) ===========
        {
            ulonglong2 ap[5];
            #pragma unroll
            for (int j = 0; j < 5; j++)
                ap[j] = *(const ulonglong2*)(affRow + (8 + j) * HWSZ);
            #pragma unroll
            for (int c = 0; c < CPT; c++) {
                const float* sr = sdy + c * (SROWS * SPITCH);
                QU q2, q3;
                q2.u = *(const ulonglong2*)(sr + 8);
                q3.u = *(const ulonglong2*)(sr + 12);
                const u64t p8 = q2.u.x, p10 = q2.u.y, p12 = q3.u.x, p14 = q3.u.y;
                const u64t p9  = packf2(q2.f.y, q2.f.z);
                const u64t p11 = packf2(q2.f.w, q3.f.x);
                const u64t p13 = packf2(q3.f.y, q3.f.z);
                accA[c] = ffma2(ap[0].x, p8,  accA[c]);  accB[c] = ffma2(ap[0].y, p10, accB[c]);
                accA[c] = ffma2(ap[1].x, p9,  accA[c]);  accB[c] = ffma2(ap[1].y, p11, accB[c]);
                accA[c] = ffma2(ap[2].x, p10, accA[c]);  accB[c] = ffma2(ap[2].y, p12, accB[c]);
                accA[c] = ffma2(ap[3].x, p11, accA[c]);  accB[c] = ffma2(ap[3].y, p13, accB[c]);
                accA[c] = ffma2(ap[4].x, p12, accA[c]);  accB[c] = ffma2(ap[4].y, p14, accB[c]);
            }
        }

        affRow += WIN * HWSZ;
        sdy    += SPITCH;
    }

    // ---- write out --------------------------------------------------------
    float* outp = out + (size_t)b * CC * HWSZ + (y0 + yy) * WW + x0 + xs
                + (size_t)c0 * HWSZ;
    #pragma unroll
    for (int c = 0; c < CPT; c++) {
        float4 v;
        unpackf2(accA[c], v.x, v.y);
        unpackf2(accB[c], v.z, v.w);
        *(float4*)(outp + (size_t)c * HWSZ) = v;
    }
}

extern "C" void kernel_launch(void* const* d_in, const int* in_sizes, int n_in,
                              void* d_out, int out_size)
{
    const float* aff = (const float*)d_in[0];   // [4,169,192,192]
    const float* in2 = (const float*)d_in[1];   // [4,64,192,192]
    float* out = (float*)d_out;                 // [4,64,192,192]

    dim3 grid(24, 12, 4);   // (cgroup*xtile, ytile, batch) — cgroup fastest for aff L2 reuse
    dim3 block(16, 16);
    mxassemble_kernel<<<grid, block>>>(aff, in2, out);
}

// round 12
// speedup vs baseline: 1.0076x; 1.0076x over previous
#include <cuda_runtime.h>

// MxAssemble: out[b,c,y,x] = sum_{dy,dx in [0,13)} aff[b, dy*13+dx, y, x] * in2zp[b, c, y+dy-6, x+dx-6]
// B=4, D=169, C=64, H=W=192, fp32.
// R6 tile shape (CBLK=16, TH=8, TW=64, CPT=8) + 12-row ring buffer for the
// y-halo: smem 61.4KB -> 3 blocks/SM (6 warps/SMSP). dx loop in 3 j-chunks
// to fit the 85-reg budget. One __syncthreads per dy (slot d refilled after
// compute(d), first re-read at dy=d+5).

#define BB   4
#define CC   64
#define HH   192
#define WW   192
#define WIN  13
#define DD   169
#define HWSZ (HH*WW)

#define TW    64     // x pixels per block
#define TH    8      // y rows per block
#define CBLK  16     // channels per block
#define CPT   8      // channels per thread
#define XR    4      // x pixels per thread
#define RROWS 12     // ring rows resident (>= 8 active + refill margin)
#define SPITCH 80    // floats per smem row (320B, 16B aligned)
#define CSTRIDE (RROWS * SPITCH)   // 960 floats between channels

typedef unsigned long long u64t;

__device__ __forceinline__ u64t ffma2(u64t a, u64t b, u64t c) {
    u64t d;
    asm("fma.rn.f32x2 %0, %1, %2, %3;" : "=l"(d) : "l"(a), "l"(b), "l"(c));
    return d;
}
__device__ __forceinline__ u64t packf2(float lo, float hi) {
    u64t d;
    asm("mov.b64 %0, {%1, %2};" : "=l"(d) : "f"(lo), "f"(hi));
    return d;
}
__device__ __forceinline__ void unpackf2(u64t v, float& lo, float& hi) {
    asm("mov.b64 {%0, %1}, %2;" : "=f"(lo), "=f"(hi) : "l"(v));
}

union QU { ulonglong2 u; float4 f; };

// load one zero-padded quad of in2 and store to smem row 'dst'
__device__ __forceinline__ void fill_quad(const float* in2c, float* dst,
                                          int gy, int gxq)
{
    float4 v = make_float4(0.f, 0.f, 0.f, 0.f);
    if ((unsigned)gy < (unsigned)HH) {
        const float* src = in2c + gy * WW + gxq;
        if (gxq >= 0 && gxq <= WW - 4) {
            v = *(const float4*)src;
        } else {
            if ((unsigned)(gxq + 0) < (unsigned)WW) v.x = src[0];
            if ((unsigned)(gxq + 1) < (unsigned)WW) v.y = src[1];
            if ((unsigned)(gxq + 2) < (unsigned)WW) v.z = src[2];
            if ((unsigned)(gxq + 3) < (unsigned)WW) v.w = src[3];
        }
    }
    const int c0q = 4 * ((gxq + 8) / 4) - 10;   // smem col of v.x (gxq = x0-8+4q -> col 4q-2)
    // (passed gxq is x0-8+4q; col computed by caller instead for clarity)
    (void)c0q;
    // caller stores; see call sites
    // NOTE: this helper only computes v; storing handled by caller
    // -- kept inline below instead --
}

__global__ __launch_bounds__(256, 3)
void mxassemble_kernel(const float* __restrict__ aff,
                       const float* __restrict__ in2,
                       float* __restrict__ out)
{
    __shared__ __align__(16) float s[CBLK][RROWS][SPITCH];   // 61,440 B

    const int tx = threadIdx.x;      // 0..15  -> x group
    const int ty = threadIdx.y;      // 0..15
    const int yy = ty & 7;           // row within tile
    const int ch = ty >> 3;          // channel half (0/1)

    const int bx = blockIdx.x;       // 12 = 4 cgroups * 3 xtiles, cgroup fastest
    const int cg = bx & 3;
    const int xt = bx >> 2;
    const int yt = blockIdx.y;       // 0..23
    const int b  = blockIdx.z;       // 0..3

    const int x0 = xt * TW;
    const int y0 = yt * TH;
    const int c0 = cg * CBLK;

    const float* in2b = in2 + (size_t)b * CC * HWSZ;
    const int tid = ty * 16 + tx;

    // ---- prologue fill: slots 0..11 <- global rows y0-6 .. y0+5 ----------
    // 3840 quads = 16 ch x 12 rows x 20 quads; idx = cc*240 + rr*20 + q.
    {
        int q  = tid % 20;
        int t2 = tid / 20;           // 0..12
        int rr = (t2 < 12) ? t2 : t2 - 12;
        int cc = (t2 < 12) ? 0 : 1;
        #pragma unroll 1
        for (int it = 0; it < 15; it++) {
            const int gy  = y0 - 6 + rr;
            const int gxq = x0 - 8 + 4 * q;

            float4 v = make_float4(0.f, 0.f, 0.f, 0.f);
            if ((unsigned)gy < (unsigned)HH) {
                const float* src = in2b + (size_t)(c0 + cc) * HWSZ + gy * WW + gxq;
                if (gxq >= 0 && gxq <= WW - 4) {
                    v = *(const float4*)src;
                } else {
                    if ((unsigned)(gxq + 0) < (unsigned)WW) v.x = src[0];
                    if ((unsigned)(gxq + 1) < (unsigned)WW) v.y = src[1];
                    if ((unsigned)(gxq + 2) < (unsigned)WW) v.z = src[2];
                    if ((unsigned)(gxq + 3) < (unsigned)WW) v.w = src[3];
                }
            }
            const int c0q = 4 * q - 2;
            float* dst = &s[cc][rr][0];
            if (c0q >= 0) *(float2*)(dst + c0q) = make_float2(v.x, v.y);
            *(float2*)(dst + c0q + 2) = make_float2(v.z, v.w);

            // advance 256 quads = +16 q, +12 rows (with carries), rows mod 12
            q += 16; int add = 12;
            if (q >= 20) { q -= 20; add = 13; }
            rr += add;
            if (rr >= 24)      { rr -= 24; cc += 2; }
            else               { rr -= 12; cc += 1; }
        }
    }
    __syncthreads();

    // ---- main loop --------------------------------------------------------
    u64t accA[CPT], accB[CPT];       // accA: outputs (xs, xs+1), accB: (xs+2, xs+3)
    #pragma unroll
    for (int c = 0; c < CPT; c++) { accA[c] = 0ull; accB[c] = 0ull; }

    const int xs = tx * XR;
    const float* affRow = aff + (size_t)b * DD * HWSZ + (y0 + yy) * WW + x0 + xs;
    const float* sch = &s[ch * CPT][0][0] + xs;   // channel-half base

    #pragma unroll 1
    for (int dy = 0; dy < WIN; dy++) {
        int rowoff = yy + dy;
        if (rowoff >= RROWS) rowoff -= RROWS;
        const float* sdy = sch + rowoff * SPITCH;

        // ======== chunk A: j = 0..3  (cols xs..xs+6 -> Q0,Q1) ==============
        {
            ulonglong2 ap[4];
            #pragma unroll
            for (int j = 0; j < 4; j++)
                ap[j] = *(const ulonglong2*)(affRow + j * HWSZ);
            #pragma unroll
            for (int c = 0; c < CPT; c++) {
                const float* sr = sdy + c * CSTRIDE;
                QU q0, q1;
                q0.u = *(const ulonglong2*)(sr);
                q1.u = *(const ulonglong2*)(sr + 4);
                const u64t p0 = q0.u.x, p2 = q0.u.y, p4 = q1.u.x;
                const u64t p1 = packf2(q0.f.y, q0.f.z);
                const u64t p3 = packf2(q0.f.w, q1.f.x);
                const u64t p5 = packf2(q1.f.y, q1.f.z);
                accA[c] = ffma2(ap[0].x, p0, accA[c]);  accB[c] = ffma2(ap[0].y, p2, accB[c]);
                accA[c] = ffma2(ap[1].x, p1, accA[c]);  accB[c] = ffma2(ap[1].y, p3, accB[c]);
                accA[c] = ffma2(ap[2].x, p2, accA[c]);  accB[c] = ffma2(ap[2].y, p4, accB[c]);
                accA[c] = ffma2(ap[3].x, p3, accA[c]);  accB[c] = ffma2(ap[3].y, p5, accB[c]);
            }
        }
        // ======== chunk B: j = 4..7  (cols xs+4..xs+10 -> Q1,Q2) ===========
        {
            ulonglong2 ap[4];
            #pragma unroll
            for (int j = 0; j < 4; j++)
                ap[j] = *(const ulonglong2*)(affRow + (4 + j) * HWSZ);
            #pragma unroll
            for (int c = 0; c < CPT; c++) {
                const float* sr = sdy + c * CSTRIDE;
                QU q1, q2;
                q1.u = *(const ulonglong2*)(sr + 4);
                q2.u = *(const ulonglong2*)(sr + 8);
                const u64t p4 = q1.u.x, p6 = q1.u.y, p8 = q2.u.x;
                const u64t p5 = packf2(q1.f.y, q1.f.z);
                const u64t p7 = packf2(q1.f.w, q2.f.x);
                const u64t p9 = packf2(q2.f.y, q2.f.z);
                accA[c] = ffma2(ap[0].x, p4, accA[c]);  accB[c] = ffma2(ap[0].y, p6, accB[c]);
                accA[c] = ffma2(ap[1].x, p5, accA[c]);  accB[c] = ffma2(ap[1].y, p7, accB[c]);
                accA[c] = ffma2(ap[2].x, p6, accA[c]);  accB[c] = ffma2(ap[2].y, p8, accB[c]);
                accA[c] = ffma2(ap[3].x, p7, accA[c]);  accB[c] = ffma2(ap[3].y, p9, accB[c]);
            }
        }
        // ======== chunk C: j = 8..12 (cols xs+8..xs+15 -> Q2,Q3) ===========
        {
            ulonglong2 ap[5];
            #pragma unroll
            for (int j = 0; j < 5; j++)
                ap[j] = *(const ulonglong2*)(affRow + (8 + j) * HWSZ);
            #pragma unroll
            for (int c = 0; c < CPT; c++) {
                const float* sr = sdy + c * CSTRIDE;
                QU q2, q3;
                q2.u = *(const ulonglong2*)(sr + 8);
                q3.u = *(const ulonglong2*)(sr + 12);
                const u64t p8 = q2.u.x, p10 = q2.u.y, p12 = q3.u.x, p14 = q3.u.y;
                const u64t p9  = packf2(q2.f.y, q2.f.z);
                const u64t p11 = packf2(q2.f.w, q3.f.x);
                const u64t p13 = packf2(q3.f.y, q3.f.z);
                accA[c] = ffma2(ap[0].x, p8,  accA[c]);  accB[c] = ffma2(ap[0].y, p10, accB[c]);
                accA[c] = ffma2(ap[1].x, p9,  accA[c]);  accB[c] = ffma2(ap[1].y, p11, accB[c]);
                accA[c] = ffma2(ap[2].x, p10, accA[c]);  accB[c] = ffma2(ap[2].y, p12, accB[c]);
                accA[c] = ffma2(ap[3].x, p11, accA[c]);  accB[c] = ffma2(ap[3].y, p13, accB[c]);
                accA[c] = ffma2(ap[4].x, p12, accA[c]);  accB[c] = ffma2(ap[4].y, p14, accB[c]);
            }
        }

        affRow += WIN * HWSZ;

        // ---- ring refill: slot dy <- global row y0+6+dy (needed at dy+5) --
        if (dy < 8) {
            __syncthreads();   // slot dy dead after compute(dy); safe to overwrite
            // 320 quads = 16 ch x 20 quads; thread tid does idx {tid, tid+256}
            const int gy = y0 + 6 + dy;
            int q  = tid % 20;
            int cc = tid / 20;          // 0..12
            #pragma unroll
            for (int pass = 0; pass < 2; pass++) {
                if (cc < CBLK) {
                    const int gxq = x0 - 8 + 4 * q;
                    float4 v = make_float4(0.f, 0.f, 0.f, 0.f);
                    if ((unsigned)gy < (unsigned)HH) {
                        const float* src = in2b + (size_t)(c0 + cc) * HWSZ + gy * WW + gxq;
                        if (gxq >= 0 && gxq <= WW - 4) {
                            v = *(const float4*)src;
                        } else {
                            if ((unsigned)(gxq + 0) < (unsigned)WW) v.x = src[0];
                            if ((unsigned)(gxq + 1) < (unsigned)WW) v.y = src[1];
                            if ((unsigned)(gxq + 2) < (unsigned)WW) v.z = src[2];
                            if ((unsigned)(gxq + 3) < (unsigned)WW) v.w = src[3];
                        }
                    }
                    const int c0q = 4 * q - 2;
                    float* dst = &s[cc][dy][0];
                    if (c0q >= 0) *(float2*)(dst + c0q) = make_float2(v.x, v.y);
                    *(float2*)(dst + c0q + 2) = make_float2(v.z, v.w);
                }
                // advance 256 quads: +16 q (+carry), +12 ch
                q += 16; cc += 12;
                if (q >= 20) { q -= 20; cc += 1; }
            }
            // no second barrier needed: slot dy first re-read at dy+5, and the
            // pre-fill barriers of dy+1..dy+4 order these writes before that read
        }
    }

    // ---- write out --------------------------------------------------------
    float* outp = out + (size_t)b * CC * HWSZ + (y0 + yy) * WW + x0 + xs
                + (size_t)(c0 + ch * CPT) * HWSZ;
    #pragma unroll
    for (int c = 0; c < CPT; c++) {
        float4 v;
        unpackf2(accA[c], v.x, v.y);
        unpackf2(accB[c], v.z, v.w);
        *(float4*)(outp + (size_t)c * HWSZ) = v;
    }
}

extern "C" void kernel_launch(void* const* d_in, const int* in_sizes, int n_in,
                              void* d_out, int out_size)
{
    const float* aff = (const float*)d_in[0];   // [4,169,192,192]
    const float* in2 = (const float*)d_in[1];   // [4,64,192,192]
    float* out = (float*)d_out;                 // [4,64,192,192]

    dim3 grid(12, 24, 4);   // (cgroup*xtile, ytile, batch) — cgroup fastest for aff L2 reuse
    dim3 block(16, 16);
    mxassemble_kernel<<<grid, block>>>(aff, in2, out);
}

// round 13
// speedup vs baseline: 1.5929x; 1.5808x over previous
#include <cuda_runtime.h>

// MxAssemble: out[b,c,y,x] = sum_{dy,dx in [0,13)} aff[b, dy*13+dx, y, x] * in2zp[b, c, y+dy-6, x+dx-6]
// B=4, D=169, C=64, H=W=192, fp32.
// Occupancy 5 blocks x 128 threads (20 warps/SM, 102-reg budget, spill-free):
// tile 32x x 8y x 16ch, CPT=8, 12-row ring buffer (36KB smem), dx in 3 j-chunks.

#define BB   4
#define CC   64
#define HH   192
#define WW   192
#define WIN  13
#define DD   169
#define HWSZ (HH*WW)

#define TW    32     // x pixels per block
#define TH    8      // y rows per block
#define CBLK  16     // channels per block
#define CPT   8      // channels per thread
#define XR    4      // x pixels per thread
#define RROWS 12     // ring rows resident
#define SPITCH 48    // floats per smem row (192B, 16B aligned); cols 0..43 data
#define NQ    12     // aligned quads per row (gxq = x0-8+4q, q=0..11)
#define CSTRIDE (RROWS * SPITCH)

typedef unsigned long long u64t;

__device__ __forceinline__ u64t ffma2(u64t a, u64t b, u64t c) {
    u64t d;
    asm("fma.rn.f32x2 %0, %1, %2, %3;" : "=l"(d) : "l"(a), "l"(b), "l"(c));
    return d;
}
__device__ __forceinline__ u64t packf2(float lo, float hi) {
    u64t d;
    asm("mov.b64 %0, {%1, %2};" : "=l"(d) : "f"(lo), "f"(hi));
    return d;
}
__device__ __forceinline__ void unpackf2(u64t v, float& lo, float& hi) {
    asm("mov.b64 {%0, %1}, %2;" : "=f"(lo), "=f"(hi) : "l"(v));
}

union QU { ulonglong2 u; float4 f; };

__global__ __launch_bounds__(128, 5)
void mxassemble_kernel(const float* __restrict__ aff,
                       const float* __restrict__ in2,
                       float* __restrict__ out)
{
    __shared__ __align__(16) float s[CBLK][RROWS][SPITCH];   // 36,864 B

    const int tx = threadIdx.x;      // 0..7   -> x group
    const int ty = threadIdx.y;      // 0..15
    const int yy = ty & 7;           // row within tile
    const int ch = ty >> 3;          // channel half (0/1)

    const int bx = blockIdx.x;       // 24 = 4 cgroups * 6 xtiles, cgroup fastest
    const int cg = bx & 3;
    const int xt = bx >> 2;
    const int yt = blockIdx.y;       // 0..23
    const int b  = blockIdx.z;       // 0..3

    const int x0 = xt * TW;
    const int y0 = yt * TH;
    const int c0 = cg * CBLK;

    const float* in2b = in2 + (size_t)b * CC * HWSZ;
    const int tid = ty * 8 + tx;     // 0..127

    // ---- prologue fill: slots 0..11 <- global rows y0-6 .. y0+5 ----------
    // 2304 quads = 16 ch x 12 rows x 12 q ; idx = cc*144 + rr*12 + q.
    {
        int q  = tid % 12;
        int t2 = tid / 12;           // 0..10
        int rr = t2;                 // < 12
        int cc = 0;
        #pragma unroll 1
        for (int it = 0; it < 18; it++) {
            const int gy  = y0 - 6 + rr;
            const int gxq = x0 - 8 + 4 * q;

            float4 v = make_float4(0.f, 0.f, 0.f, 0.f);
            if ((unsigned)gy < (unsigned)HH) {
                const float* src = in2b + (size_t)(c0 + cc) * HWSZ + gy * WW + gxq;
                if (gxq >= 0 && gxq <= WW - 4) {
                    v = *(const float4*)src;
                } else {
                    if ((unsigned)(gxq + 0) < (unsigned)WW) v.x = src[0];
                    if ((unsigned)(gxq + 1) < (unsigned)WW) v.y = src[1];
                    if ((unsigned)(gxq + 2) < (unsigned)WW) v.z = src[2];
                    if ((unsigned)(gxq + 3) < (unsigned)WW) v.w = src[3];
                }
            }
            const int c0q = 4 * q - 2;               // smem col of v.x
            float* dst = &s[cc][rr][0];
            if (c0q >= 0) *(float2*)(dst + c0q) = make_float2(v.x, v.y);
            *(float2*)(dst + c0q + 2) = make_float2(v.z, v.w);

            // advance 128 quads = 10*12 + 8
            q += 8; int add = 10;
            if (q >= 12) { q -= 12; add = 11; }
            rr += add;
            if (rr >= 12) { rr -= 12; cc += 1; }
        }
    }
    __syncthreads();

    // ---- main loop --------------------------------------------------------
    u64t accA[CPT], accB[CPT];       // accA: outputs (xs, xs+1), accB: (xs+2, xs+3)
    #pragma unroll
    for (int c = 0; c < CPT; c++) { accA[c] = 0ull; accB[c] = 0ull; }

    const int xs = tx * XR;          // 0..28
    const float* affRow = aff + (size_t)b * DD * HWSZ + (y0 + yy) * WW + x0 + xs;
    const float* sch = &s[ch * CPT][0][0] + xs;   // channel-half base

    #pragma unroll 1
    for (int dy = 0; dy < WIN; dy++) {
        int rowoff = yy + dy;
        if (rowoff >= RROWS) rowoff -= RROWS;
        const float* sdy = sch + rowoff * SPITCH;

        // ======== chunk A: j = 0..3  (cols xs..xs+6 -> Q0,Q1) ==============
        {
            ulonglong2 ap[4];
            #pragma unroll
            for (int j = 0; j < 4; j++)
                ap[j] = *(const ulonglong2*)(affRow + j * HWSZ);
            #pragma unroll
            for (int c = 0; c < CPT; c++) {
                const float* sr = sdy + c * CSTRIDE;
                QU q0, q1;
                q0.u = *(const ulonglong2*)(sr);
                q1.u = *(const ulonglong2*)(sr + 4);
                const u64t p0 = q0.u.x, p2 = q0.u.y, p4 = q1.u.x;
                const u64t p1 = packf2(q0.f.y, q0.f.z);
                const u64t p3 = packf2(q0.f.w, q1.f.x);
                const u64t p5 = packf2(q1.f.y, q1.f.z);
                accA[c] = ffma2(ap[0].x, p0, accA[c]);  accB[c] = ffma2(ap[0].y, p2, accB[c]);
                accA[c] = ffma2(ap[1].x, p1, accA[c]);  accB[c] = ffma2(ap[1].y, p3, accB[c]);
                accA[c] = ffma2(ap[2].x, p2, accA[c]);  accB[c] = ffma2(ap[2].y, p4, accB[c]);
                accA[c] = ffma2(ap[3].x, p3, accA[c]);  accB[c] = ffma2(ap[3].y, p5, accB[c]);
            }
        }
        // ======== chunk B: j = 4..7  (cols xs+4..xs+10 -> Q1,Q2) ===========
        {
            ulonglong2 ap[4];
            #pragma unroll
            for (int j = 0; j < 4; j++)
                ap[j] = *(const ulonglong2*)(affRow + (4 + j) * HWSZ);
            #pragma unroll
            for (int c = 0; c < CPT; c++) {
                const float* sr = sdy + c * CSTRIDE;
                QU q1, q2;
                q1.u = *(const ulonglong2*)(sr + 4);
                q2.u = *(const ulonglong2*)(sr + 8);
                const u64t p4 = q1.u.x, p6 = q1.u.y, p8 = q2.u.x;
                const u64t p5 = packf2(q1.f.y, q1.f.z);
                const u64t p7 = packf2(q1.f.w, q2.f.x);
                const u64t p9 = packf2(q2.f.y, q2.f.z);
                accA[c] = ffma2(ap[0].x, p4, accA[c]);  accB[c] = ffma2(ap[0].y, p6, accB[c]);
                accA[c] = ffma2(ap[1].x, p5, accA[c]);  accB[c] = ffma2(ap[1].y, p7, accB[c]);
                accA[c] = ffma2(ap[2].x, p6, accA[c]);  accB[c] = ffma2(ap[2].y, p8, accB[c]);
                accA[c] = ffma2(ap[3].x, p7, accA[c]);  accB[c] = ffma2(ap[3].y, p9, accB[c]);
            }
        }
        // ======== chunk C: j = 8..12 (cols xs+8..xs+15 -> Q2,Q3) ===========
        {
            ulonglong2 ap[5];
            #pragma unroll
            for (int j = 0; j < 5; j++)
                ap[j] = *(const ulonglong2*)(affRow + (8 + j) * HWSZ);
            #pragma unroll
            for (int c = 0; c < CPT; c++) {
                const float* sr = sdy + c * CSTRIDE;
                QU q2, q3;
                q2.u = *(const ulonglong2*)(sr + 8);
                q3.u = *(const ulonglong2*)(sr + 12);
                const u64t p8 = q2.u.x, p10 = q2.u.y, p12 = q3.u.x, p14 = q3.u.y;
                const u64t p9  = packf2(q2.f.y, q2.f.z);
                const u64t p11 = packf2(q2.f.w, q3.f.x);
                const u64t p13 = packf2(q3.f.y, q3.f.z);
                accA[c] = ffma2(ap[0].x, p8,  accA[c]);  accB[c] = ffma2(ap[0].y, p10, accB[c]);
                accA[c] = ffma2(ap[1].x, p9,  accA[c]);  accB[c] = ffma2(ap[1].y, p11, accB[c]);
                accA[c] = ffma2(ap[2].x, p10, accA[c]);  accB[c] = ffma2(ap[2].y, p12, accB[c]);
                accA[c] = ffma2(ap[3].x, p11, accA[c]);  accB[c] = ffma2(ap[3].y, p13, accB[c]);
                accA[c] = ffma2(ap[4].x, p12, accA[c]);  accB[c] = ffma2(ap[4].y, p14, accB[c]);
            }
        }

        affRow += WIN * HWSZ;

        // ---- ring refill: slot dy <- global row y0+6+dy (first read dy+5) --
        if (dy < 8) {
            __syncthreads();   // slot dy dead after compute(dy); safe to overwrite
            // 192 quads = 16 ch x 12 q ; thread tid does idx {tid, tid+128}
            const int gy = y0 + 6 + dy;
            int q  = tid % 12;
            int cc = tid / 12;          // 0..10
            #pragma unroll
            for (int pass = 0; pass < 2; pass++) {
                if (cc < CBLK) {
                    const int gxq = x0 - 8 + 4 * q;
                    float4 v = make_float4(0.f, 0.f, 0.f, 0.f);
                    if ((unsigned)gy < (unsigned)HH) {
                        const float* src = in2b + (size_t)(c0 + cc) * HWSZ + gy * WW + gxq;
                        if (gxq >= 0 && gxq <= WW - 4) {
                            v = *(const float4*)src;
                        } else {
                            if ((unsigned)(gxq + 0) < (unsigned)WW) v.x = src[0];
                            if ((unsigned)(gxq + 1) < (unsigned)WW) v.y = src[1];
                            if ((unsigned)(gxq + 2) < (unsigned)WW) v.z = src[2];
                            if ((unsigned)(gxq + 3) < (unsigned)WW) v.w = src[3];
                        }
                    }
                    const int c0q = 4 * q - 2;
                    float* dst = &s[cc][dy][0];
                    if (c0q >= 0) *(float2*)(dst + c0q) = make_float2(v.x, v.y);
                    *(float2*)(dst + c0q + 2) = make_float2(v.z, v.w);
                }
                // advance 128 quads: +8 q (+carry), +10 ch
                q += 8; cc += 10;
                if (q >= 12) { q -= 12; cc += 1; }
            }
            // writes to slot dy ordered before first read (dy+5) by the
            // pre-refill barriers of iterations dy+1..dy+4
        }
    }

    // ---- write out --------------------------------------------------------
    float* outp = out + (size_t)b * CC * HWSZ + (y0 + yy) * WW + x0 + xs
                + (size_t)(c0 + ch * CPT) * HWSZ;
    #pragma unroll
    for (int c = 0; c < CPT; c++) {
        float4 v;
        unpackf2(accA[c], v.x, v.y);
        unpackf2(accB[c], v.z, v.w);
        *(float4*)(outp + (size_t)c * HWSZ) = v;
    }
}

extern "C" void kernel_launch(void* const* d_in, const int* in_sizes, int n_in,
                              void* d_out, int out_size)
{
    const float* aff = (const float*)d_in[0];   // [4,169,192,192]
    const float* in2 = (const float*)d_in[1];   // [4,64,192,192]
    float* out = (float*)d_out;                 // [4,64,192,192]

    dim3 grid(24, 24, 4);   // (cgroup*xtile, ytile, batch) — cgroup fastest for aff L2 reuse
    dim3 block(8, 16);      // 128 threads, 5 blocks/SM
    mxassemble_kernel<<<grid, block>>>(aff, in2, out);
}